// round 1
// baseline (speedup 1.0000x reference)
#include <cuda_runtime.h>
#include <math.h>

#define H 2048
#define HH (H*H)
#define TILE 32
#define HALO 2
#define IN_W (TILE + 2*HALO)   // 36
#define YW   (TILE + 2)        // 34

// Read a device int scalar if pointer non-null, else default.
__device__ __forceinline__ int dscalar(const int* p, int def) {
    return p ? p[0] : def;
}

__global__ __launch_bounds__(256)
void pgonet_main(const float* __restrict__ ref_speed,
                 const float* __restrict__ batch,
                 const float* __restrict__ x_tt,
                 const float* __restrict__ x_t,
                 const float* __restrict__ conv_v,
                 const float* __restrict__ conv_g,
                 const float* __restrict__ conv_b,
                 const int*   __restrict__ p_bsize,
                 const int*   __restrict__ p_flag,
                 const int*   __restrict__ p_flag_num,
                 float* __restrict__ out)
{
    __shared__ float s_in[3 * IN_W * IN_W];   // ch0=xtt ch1=xt ch2=speed
    __shared__ float s_y[YW * IN_W];          // conv output tile (stride IN_W)
    __shared__ float s_W[27];
    __shared__ float s_b;

    const int tx = threadIdx.x, ty = threadIdx.y;
    const int tid = ty * 32 + tx;
    const int r0 = blockIdx.y * TILE;
    const int c0 = blockIdx.x * TILE;

    // batch plane offsets (every thread; broadcast loads, cheap)
    const int bsize = dscalar(p_bsize, 10);
    const int ntb   = dscalar(p_flag, 1) - 1;
    const int step  = dscalar(p_flag_num, 1) - 1;
    const int i0    = ntb * bsize + step;
    const float* __restrict__ xtt_g = batch + (size_t)i0 * HH;
    const float* __restrict__ xt_g  = batch + (size_t)(i0 + 1) * HH;

    // normalized conv weights (one thread; tiny)
    if (tid == 0) {
        float ss = 0.f;
        #pragma unroll
        for (int i = 0; i < 27; i++) { float v = conv_v[i]; ss += v * v; }
        float scale = conv_g[0] / sqrtf(ss);
        #pragma unroll
        for (int i = 0; i < 27; i++) s_W[i] = conv_v[i] * scale;
        s_b = conv_b[0];
    }

    // stage 36x36 tiles of {xtt, xt, speed} with zero padding
    for (int idx = tid; idx < 3 * IN_W * IN_W; idx += 256) {
        int ch = idx / (IN_W * IN_W);
        int k  = idx - ch * (IN_W * IN_W);
        int lr = k / IN_W, lc = k - lr * IN_W;
        int gr = r0 - HALO + lr, gc = c0 - HALO + lc;
        float v = 0.f;
        if (gr >= 0 && gr < H && gc >= 0 && gc < H) {
            const float* p = (ch == 0) ? xtt_g : ((ch == 1) ? xt_g : ref_speed);
            v = p[(size_t)gr * H + gc];
        }
        s_in[idx] = v;
    }
    __syncthreads();

    // weights to registers (broadcast LDS once)
    float w[27];
    #pragma unroll
    for (int i = 0; i < 27; i++) w[i] = s_W[i];
    const float bconv = s_b;

    // compute y on 34x34 tile: y local (lr,lc) -> global (r0-1+lr, c0-1+lc)
    for (int idx = tid; idx < YW * YW; idx += 256) {
        int lr = idx / YW, lc = idx - lr * YW;
        float acc = bconv;
        #pragma unroll
        for (int ch = 0; ch < 3; ch++) {
            const float* base = s_in + ch * (IN_W * IN_W) + lr * IN_W + lc;
            #pragma unroll
            for (int kh = 0; kh < 3; kh++)
                #pragma unroll
                for (int kw = 0; kw < 3; kw++)
                    acc = fmaf(w[ch * 9 + kh * 3 + kw], base[kh * IN_W + kw], acc);
        }
        s_y[lr * IN_W + lc] = acc;
    }
    __syncthreads();

    const float* s_xtt = s_in;
    const float* s_xt  = s_in + IN_W * IN_W;
    const float* s_sp  = s_in + 2 * IN_W * IN_W;

    #pragma unroll
    for (int q = 0; q < 4; q++) {
        int pr = ty + q * 8, pc = tx;
        int r = r0 + pr, c = c0 + pc;
        int ii = (pr + HALO) * IN_W + (pc + HALO);

        float xt_c  = s_xt[ii];
        float xtt_c = s_xtt[ii];
        float sp    = s_sp[ii];
        float coef  = sp * sp * 0.0025f;          // DT^2/DX^2
        bool interior = (r > 0) & (r < H - 1) & (c > 0) & (c < H - 1);
        float base = 2.f * xt_c - xtt_c;

        // x_t4 (plane 6)
        float xt4 = 0.f;
        if (interior) {
            float lap = s_xt[ii - IN_W] + s_xt[ii + IN_W]
                      + s_xt[ii - 1]    + s_xt[ii + 1] - 4.f * xt_c;
            xt4 = base + lap * coef;
        }

        // x7_pre (plane 5)
        int yi = (pr + 1) * IN_W + (pc + 1);
        float yc = s_y[yi];
        float x7p;
        if (interior) {
            float lapy = s_y[yi - IN_W] + s_y[yi + IN_W]
                       + s_y[yi - 1]    + s_y[yi + 1] - 4.f * yc;
            x7p = base + lapy * coef;
        } else {
            x7p = yc;
        }

        // x7 (plane 2): boundary override chain, last-wins order
        float x7v = x7p;
        if (r == 0) x7v = 0.f;
        if (c == 0) {
            float a = xt_c, bnb = s_xt[ii + 1];
            x7v = a - 0.05f * sp * (a - bnb);     // DT/DX = 0.05
        }
        if (r >= 1 && r <= H - 2 && c == H - r)
            x7v = s_xt[ii - IN_W - 1];            // xt[r-1, c-1]
        if (c == H - 1) {
            float a = xt_c, bnb = s_xt[ii - 1];
            x7v = a - 0.05f * sp * (a - bnb);
        }
        if (r == H - 1) x7v = 0.f;

        size_t g = (size_t)r * H + c;
        float vtt = x_tt[g];
        float vt  = x_t[g];
        out[g]            = vtt;
        out[HH + g]       = vt;
        out[2 * (size_t)HH + g] = x7v;
        out[3 * (size_t)HH + g] = vtt;
        out[4 * (size_t)HH + g] = vt;
        out[5 * (size_t)HH + g] = x7p;
        out[6 * (size_t)HH + g] = xt4;
    }
}

__global__ void pgonet_scatter(const float* __restrict__ ref_sol,
                               const int*   __restrict__ loc_x,
                               const int*   __restrict__ loc_y,
                               const int*   __restrict__ p_bsize,
                               const int*   __restrict__ p_id,
                               const int*   __restrict__ p_flag_num,
                               float* __restrict__ out, int P)
{
    int i = blockIdx.x * blockDim.x + threadIdx.x;
    if (i >= P) return;
    int lx = loc_x[i];
    if (lx == -1) return;                 // invalid -> no-op write of current value
    int ly = loc_y[i];
    int bsize = dscalar(p_bsize, 10);
    int id    = dscalar(p_id, 1);
    int step  = dscalar(p_flag_num, 1) - 1;
    size_t obs_off = (size_t)(id * bsize + step + 2) * HH;
    size_t g = (size_t)lx * H + ly;
    out[2 * (size_t)HH + g] = ref_sol[obs_off + g];
}

extern "C" void kernel_launch(void* const* d_in, const int* in_sizes, int n_in,
                              void* d_out, int out_size)
{
    const float* ref_speed = (const float*)d_in[0];
    const float* batch     = (const float*)d_in[1];
    const float* x_tt      = (const float*)d_in[2];
    const float* x_t       = (const float*)d_in[3];
    const float* ref_sol   = (const float*)d_in[4];
    const float* conv_v    = (const float*)d_in[5];
    const float* conv_g    = (const float*)d_in[6];
    const float* conv_b    = (const float*)d_in[7];
    const int*   loc_x     = (const int*)d_in[8];
    const int*   loc_y     = (const int*)d_in[9];
    const int* p_bsize    = (n_in > 10) ? (const int*)d_in[10] : nullptr;
    const int* p_id       = (n_in > 11) ? (const int*)d_in[11] : nullptr;
    const int* p_flag     = (n_in > 12) ? (const int*)d_in[12] : nullptr;
    const int* p_flag_num = (n_in > 13) ? (const int*)d_in[13] : nullptr;

    float* out = (float*)d_out;
    int P = in_sizes[8];

    dim3 block(32, 8);
    dim3 grid(H / TILE, H / TILE);
    pgonet_main<<<grid, block>>>(ref_speed, batch, x_tt, x_t,
                                 conv_v, conv_g, conv_b,
                                 p_bsize, p_flag, p_flag_num, out);
    pgonet_scatter<<<(P + 255) / 256, 256>>>(ref_sol, loc_x, loc_y,
                                             p_bsize, p_id, p_flag_num, out, P);
}

// round 2
// speedup vs baseline: 1.0483x; 1.0483x over previous
#include <cuda_runtime.h>
#include <math.h>

#define H 2048
#define HH (H*H)
#define TILE 32
#define IN_W 40                 // smem row stride: cols c0-4 .. c0+35
#define IN_H 36                 // rows r0-2 .. r0+33
#define YW 36                   // y tile row stride (34 used + 2 garbage)
#define YH 34

__device__ __forceinline__ int dscalar(const int* p, int def) {
    return p ? p[0] : def;
}

// ---------------------------------------------------------------------------
// Kernel 1: planes 0,1,3,4 are pure copies of x_tt / x_t. Read once, write twice.
// ---------------------------------------------------------------------------
__global__ __launch_bounds__(256)
void pgonet_copy(const float4* __restrict__ x_tt,
                 const float4* __restrict__ x_t,
                 float4* __restrict__ out)
{
    int i = blockIdx.x * blockDim.x + threadIdx.x;
    const int N4 = HH / 4;
    if (i >= N4) return;
    float4 a = x_tt[i];
    float4 b = x_t[i];
    out[i]            = a;   // plane 0
    out[N4 + i]       = b;   // plane 1
    out[3 * N4 + i]   = a;   // plane 3
    out[4 * N4 + i]   = b;   // plane 4
}

// ---------------------------------------------------------------------------
// Kernel 2: planes 2 (x7), 5 (x7_pre), 6 (x_t4)
// ---------------------------------------------------------------------------
__global__ __launch_bounds__(256)
void pgonet_main(const float* __restrict__ ref_speed,
                 const float* __restrict__ batch,
                 const float* __restrict__ conv_v,
                 const float* __restrict__ conv_g,
                 const float* __restrict__ conv_b,
                 const int*   __restrict__ p_bsize,
                 const int*   __restrict__ p_flag,
                 const int*   __restrict__ p_flag_num,
                 float* __restrict__ out)
{
    __shared__ float s_in[3 * IN_H * IN_W];   // ch0=xtt ch1=xt ch2=speed
    __shared__ float s_y[YH * YW];
    __shared__ float s_W[27];
    __shared__ float s_b;

    const int tx = threadIdx.x;   // 0..7  (float4 column group)
    const int ty = threadIdx.y;   // 0..31 (row)
    const int tid = ty * 8 + tx;
    const int r0 = blockIdx.y * TILE;
    const int c0 = blockIdx.x * TILE;

    const int bsize = dscalar(p_bsize, 10);
    const int ntb   = dscalar(p_flag, 1) - 1;
    const int step  = dscalar(p_flag_num, 1) - 1;
    const int i0    = ntb * bsize + step;
    const float* __restrict__ xtt_g = batch + (size_t)i0 * HH;
    const float* __restrict__ xt_g  = batch + (size_t)(i0 + 1) * HH;

    if (tid == 0) {
        float ss = 0.f;
        #pragma unroll
        for (int i = 0; i < 27; i++) { float v = conv_v[i]; ss += v * v; }
        float scale = conv_g[0] / sqrtf(ss);
        #pragma unroll
        for (int i = 0; i < 27; i++) s_W[i] = conv_v[i] * scale;
        s_b = conv_b[0];
    }

    // stage 3 x 36 x 40 floats as float4 (col groups are all-in or all-out of range)
    // 3 channels * 36 rows * 10 float4 = 1080 float4
    for (int idx = tid; idx < 3 * IN_H * 10; idx += 256) {
        int ch = idx / (IN_H * 10);
        int k  = idx - ch * (IN_H * 10);
        int lr = k / 10, lq = k - lr * 10;
        int gr = r0 - 2 + lr;
        int gc = c0 - 4 + lq * 4;
        float4 v = make_float4(0.f, 0.f, 0.f, 0.f);
        if (gr >= 0 && gr < H && gc >= 0 && gc + 3 < H) {
            const float* p = (ch == 0) ? xtt_g : ((ch == 1) ? xt_g : ref_speed);
            v = *reinterpret_cast<const float4*>(p + (size_t)gr * H + gc);
        }
        *reinterpret_cast<float4*>(&s_in[ch * (IN_H * IN_W) + lr * IN_W + lq * 4]) = v;
    }
    __syncthreads();

    float w[27];
    #pragma unroll
    for (int i = 0; i < 27; i++) w[i] = s_W[i];
    const float bconv = s_b;

    // conv: y rows ly=0..33 (gr = r0-1+ly), cols lyc=0..35 (gc = c0-1+lyc), 4-wide strips
    // 34 rows * 9 strips = 306 strips
    for (int idx = tid; idx < YH * 9; idx += 256) {
        int ly = idx / 9, q = idx - ly * 9;
        float acc0 = bconv, acc1 = bconv, acc2 = bconv, acc3 = bconv;
        #pragma unroll
        for (int ch = 0; ch < 3; ch++) {
            #pragma unroll
            for (int kh = 0; kh < 3; kh++) {
                const float* row = s_in + ch * (IN_H * IN_W) + (ly + kh) * IN_W + (4 * q + 2);
                float a0 = row[0], a1 = row[1], a2 = row[2];
                float a3 = row[3], a4 = row[4], a5 = row[5];
                float w0 = w[ch * 9 + kh * 3 + 0];
                float w1 = w[ch * 9 + kh * 3 + 1];
                float w2 = w[ch * 9 + kh * 3 + 2];
                acc0 = fmaf(w0, a0, acc0); acc0 = fmaf(w1, a1, acc0); acc0 = fmaf(w2, a2, acc0);
                acc1 = fmaf(w0, a1, acc1); acc1 = fmaf(w1, a2, acc1); acc1 = fmaf(w2, a3, acc1);
                acc2 = fmaf(w0, a2, acc2); acc2 = fmaf(w1, a3, acc2); acc2 = fmaf(w2, a4, acc2);
                acc3 = fmaf(w0, a3, acc3); acc3 = fmaf(w1, a4, acc3); acc3 = fmaf(w2, a5, acc3);
            }
        }
        float* yr = s_y + ly * YW + 4 * q;
        yr[0] = acc0; yr[1] = acc1; yr[2] = acc2; yr[3] = acc3;
    }
    __syncthreads();

    const float* s_xtt = s_in;
    const float* s_xt  = s_in + IN_H * IN_W;
    const float* s_sp  = s_in + 2 * IN_H * IN_W;

    // each thread: row r0+ty, cols c0+4tx .. +3
    const int r = r0 + ty;
    const int cbase = c0 + 4 * tx;
    float x7v[4], x7p[4], xt4[4];

    #pragma unroll
    for (int j = 0; j < 4; j++) {
        int c = cbase + j;
        int ii = (ty + 2) * IN_W + (4 * tx + j + 4);
        int yi = (ty + 1) * YW + (4 * tx + j + 1);

        float xt_c  = s_xt[ii];
        float xtt_c = s_xtt[ii];
        float sp    = s_sp[ii];
        float coef  = sp * sp * 0.0025f;            // DT^2/DX^2
        bool interior = (r > 0) & (r < H - 1) & (c > 0) & (c < H - 1);
        float base = 2.f * xt_c - xtt_c;

        float v4 = 0.f;
        if (interior) {
            float lap = s_xt[ii - IN_W] + s_xt[ii + IN_W]
                      + s_xt[ii - 1]    + s_xt[ii + 1] - 4.f * xt_c;
            v4 = base + lap * coef;
        }
        xt4[j] = v4;

        float yc = s_y[yi];
        float p;
        if (interior) {
            float lapy = s_y[yi - YW] + s_y[yi + YW]
                       + s_y[yi - 1]  + s_y[yi + 1] - 4.f * yc;
            p = base + lapy * coef;
        } else {
            p = yc;
        }
        x7p[j] = p;

        float v = p;
        if (r == 0) v = 0.f;
        if (c == 0) v = xt_c - 0.05f * sp * (xt_c - s_xt[ii + 1]);   // DT/DX
        if (r >= 1 && r <= H - 2 && c == H - r) v = s_xt[ii - IN_W - 1];
        if (c == H - 1) v = xt_c - 0.05f * sp * (xt_c - s_xt[ii - 1]);
        if (r == H - 1) v = 0.f;
        x7v[j] = v;
    }

    size_t g = (size_t)r * H + cbase;
    *reinterpret_cast<float4*>(out + 2 * (size_t)HH + g) = *reinterpret_cast<float4*>(x7v);
    *reinterpret_cast<float4*>(out + 5 * (size_t)HH + g) = *reinterpret_cast<float4*>(x7p);
    *reinterpret_cast<float4*>(out + 6 * (size_t)HH + g) = *reinterpret_cast<float4*>(xt4);
}

// ---------------------------------------------------------------------------
// Kernel 3: observation scatter onto plane 2 (must run after main)
// ---------------------------------------------------------------------------
__global__ void pgonet_scatter(const float* __restrict__ ref_sol,
                               const int*   __restrict__ loc_x,
                               const int*   __restrict__ loc_y,
                               const int*   __restrict__ p_bsize,
                               const int*   __restrict__ p_id,
                               const int*   __restrict__ p_flag_num,
                               float* __restrict__ out, int P)
{
    int i = blockIdx.x * blockDim.x + threadIdx.x;
    if (i >= P) return;
    int lx = loc_x[i];
    if (lx == -1) return;
    int ly = loc_y[i];
    int bsize = dscalar(p_bsize, 10);
    int id    = dscalar(p_id, 1);
    int step  = dscalar(p_flag_num, 1) - 1;
    size_t obs_off = (size_t)(id * bsize + step + 2) * HH;
    size_t g = (size_t)lx * H + ly;
    out[2 * (size_t)HH + g] = ref_sol[obs_off + g];
}

extern "C" void kernel_launch(void* const* d_in, const int* in_sizes, int n_in,
                              void* d_out, int out_size)
{
    const float* ref_speed = (const float*)d_in[0];
    const float* batch     = (const float*)d_in[1];
    const float* x_tt      = (const float*)d_in[2];
    const float* x_t       = (const float*)d_in[3];
    const float* ref_sol   = (const float*)d_in[4];
    const float* conv_v    = (const float*)d_in[5];
    const float* conv_g    = (const float*)d_in[6];
    const float* conv_b    = (const float*)d_in[7];
    const int*   loc_x     = (const int*)d_in[8];
    const int*   loc_y     = (const int*)d_in[9];
    const int* p_bsize    = (n_in > 10) ? (const int*)d_in[10] : nullptr;
    const int* p_id       = (n_in > 11) ? (const int*)d_in[11] : nullptr;
    const int* p_flag     = (n_in > 12) ? (const int*)d_in[12] : nullptr;
    const int* p_flag_num = (n_in > 13) ? (const int*)d_in[13] : nullptr;

    float* out = (float*)d_out;
    int P = in_sizes[8];

    // copy kernel: HH/4 float4 elements
    int n4 = HH / 4;
    pgonet_copy<<<(n4 + 255) / 256, 256>>>((const float4*)x_tt, (const float4*)x_t,
                                           (float4*)out);

    dim3 block(8, 32);
    dim3 grid(H / TILE, H / TILE);
    pgonet_main<<<grid, block>>>(ref_speed, batch,
                                 conv_v, conv_g, conv_b,
                                 p_bsize, p_flag, p_flag_num, out);
    pgonet_scatter<<<(P + 255) / 256, 256>>>(ref_sol, loc_x, loc_y,
                                             p_bsize, p_id, p_flag_num, out, P);
}

// round 3
// speedup vs baseline: 1.3720x; 1.3088x over previous
#include <cuda_runtime.h>
#include <math.h>

#define H 2048
#define HH (H*H)
#define TW 64                  // tile width (cols)
#define TH 32                  // tile height (rows)
#define IN_W 72                // smem input row stride: cols c0-4 .. c0+67
#define IN_H 36                // rows r0-2 .. r0+33
#define YW 72                  // y smem stride (y col lyc stored at lyc+3)
#define YH 34

__device__ __forceinline__ int dscalar(const int* p, int def) {
    return p ? p[0] : def;
}

// ---------------------------------------------------------------------------
// Kernel 1: planes 0,1,3,4 are pure copies of x_tt / x_t (read once, write twice)
// ---------------------------------------------------------------------------
__global__ __launch_bounds__(256)
void pgonet_copy(const float4* __restrict__ x_tt,
                 const float4* __restrict__ x_t,
                 float4* __restrict__ out)
{
    int i = blockIdx.x * 256 + threadIdx.x;
    const int N4 = HH / 4;
    if (i >= N4) return;
    float4 a = x_tt[i];
    float4 b = x_t[i];
    out[i]          = a;   // plane 0
    out[N4 + i]     = b;   // plane 1
    out[3 * N4 + i] = a;   // plane 3
    out[4 * N4 + i] = b;   // plane 4
}

// ---------------------------------------------------------------------------
// Kernel 2: planes 2 (x7), 5 (x7_pre), 6 (x_t4), with obs-scatter folded in
// ---------------------------------------------------------------------------
__global__ __launch_bounds__(512, 3)
void pgonet_main(const float* __restrict__ ref_speed,
                 const float* __restrict__ batch,
                 const float* __restrict__ conv_v,
                 const float* __restrict__ conv_g,
                 const float* __restrict__ conv_b,
                 const float* __restrict__ ref_sol,
                 const int*   __restrict__ loc_x,
                 const int*   __restrict__ loc_y,
                 const int* p_bsize, const int* p_id,
                 const int* p_flag, const int* p_flag_num,
                 float* __restrict__ out, int P)
{
    __shared__ float s_in[3 * IN_H * IN_W];   // ch0=xtt ch1=xt ch2=speed
    __shared__ float s_y[YH * YW];
    __shared__ float s_W[27];
    __shared__ float s_b;

    const int tx = threadIdx.x;   // 0..15 (float4 col group)
    const int ty = threadIdx.y;   // 0..31 (row)
    const int tid = ty * 16 + tx;
    const int r0 = blockIdx.y * TH;
    const int c0 = blockIdx.x * TW;

    const int bsize = dscalar(p_bsize, 10);
    const int ntb   = dscalar(p_flag, 1) - 1;
    const int step  = dscalar(p_flag_num, 1) - 1;
    const int i0    = ntb * bsize + step;
    const float* __restrict__ xtt_g = batch + (size_t)i0 * HH;
    const float* __restrict__ xt_g  = batch + (size_t)(i0 + 1) * HH;

    if (tid == 0) {
        float ss = 0.f;
        #pragma unroll
        for (int i = 0; i < 27; i++) { float v = conv_v[i]; ss += v * v; }
        float scale = conv_g[0] / sqrtf(ss);
        #pragma unroll
        for (int i = 0; i < 27; i++) s_W[i] = conv_v[i] * scale;
        s_b = conv_b[0];
    }

    // stage 3 x 36 x 72 floats as float4: 3*36*18 = 1944 float4
    for (int idx = tid; idx < 3 * IN_H * 18; idx += 512) {
        int ch = idx / (IN_H * 18);
        int k  = idx - ch * (IN_H * 18);
        int lr = k / 18, lq = k - lr * 18;
        int gr = r0 - 2 + lr;
        int gc = c0 - 4 + lq * 4;
        float4 v = make_float4(0.f, 0.f, 0.f, 0.f);
        if (gr >= 0 && gr < H && gc >= 0 && gc + 3 < H) {
            const float* p = (ch == 0) ? xtt_g : ((ch == 1) ? xt_g : ref_speed);
            v = *reinterpret_cast<const float4*>(p + (size_t)gr * H + gc);
        }
        *reinterpret_cast<float4*>(&s_in[ch * (IN_H * IN_W) + lr * IN_W + lq * 4]) = v;
    }
    __syncthreads();

    const float bconv = s_b;

    // conv: y rows ly=0..33 (gr=r0-1+ly), y cols lyc=0..67 (gc=c0-1+lyc)
    // 34 rows * 17 four-wide strips = 578
    for (int idx = tid; idx < YH * 17; idx += 512) {
        int ly = idx / 17, q = idx - ly * 17;
        float acc0 = bconv, acc1 = bconv, acc2 = bconv, acc3 = bconv;
        #pragma unroll
        for (int ch = 0; ch < 3; ch++) {
            #pragma unroll
            for (int kh = 0; kh < 3; kh++) {
                const float4* rp = reinterpret_cast<const float4*>(
                    s_in + ch * (IN_H * IN_W) + (ly + kh) * IN_W + 4 * q);
                float4 A = rp[0], B = rp[1];
                // taps a0..a5 at input cols 4q+2 .. 4q+7
                float w0 = s_W[ch * 9 + kh * 3 + 0];
                float w1 = s_W[ch * 9 + kh * 3 + 1];
                float w2 = s_W[ch * 9 + kh * 3 + 2];
                acc0 = fmaf(w0, A.z, acc0); acc0 = fmaf(w1, A.w, acc0); acc0 = fmaf(w2, B.x, acc0);
                acc1 = fmaf(w0, A.w, acc1); acc1 = fmaf(w1, B.x, acc1); acc1 = fmaf(w2, B.y, acc1);
                acc2 = fmaf(w0, B.x, acc2); acc2 = fmaf(w1, B.y, acc2); acc2 = fmaf(w2, B.z, acc2);
                acc3 = fmaf(w0, B.y, acc3); acc3 = fmaf(w1, B.z, acc3); acc3 = fmaf(w2, B.w, acc3);
            }
        }
        float* yr = s_y + ly * YW + 4 * q + 3;    // +3 col shift for aligned reads
        yr[0] = acc0; yr[1] = acc1; yr[2] = acc2; yr[3] = acc3;
    }
    __syncthreads();

    const float* s_xtt = s_in;
    const float* s_xt  = s_in + IN_H * IN_W;
    const float* s_sp  = s_in + 2 * IN_H * IN_W;

    // each thread: row r0+ty, cols c0+4tx .. +3
    const int r = r0 + ty;
    const int cb = c0 + 4 * tx;

    // vector smem reads (all 16B aligned)
    float4 xtC  = *reinterpret_cast<const float4*>(s_xt  + (ty + 2) * IN_W + 4 * tx + 4);
    float4 xtU  = *reinterpret_cast<const float4*>(s_xt  + (ty + 1) * IN_W + 4 * tx + 4);
    float4 xtD  = *reinterpret_cast<const float4*>(s_xt  + (ty + 3) * IN_W + 4 * tx + 4);
    float  xtL  = s_xt[(ty + 2) * IN_W + 4 * tx + 3];
    float  xtR  = s_xt[(ty + 2) * IN_W + 4 * tx + 8];
    float4 xttC = *reinterpret_cast<const float4*>(s_xtt + (ty + 2) * IN_W + 4 * tx + 4);
    float4 spC  = *reinterpret_cast<const float4*>(s_sp  + (ty + 2) * IN_W + 4 * tx + 4);
    float4 yC   = *reinterpret_cast<const float4*>(s_y + (ty + 1) * YW + 4 * tx + 4);
    float4 yU   = *reinterpret_cast<const float4*>(s_y + (ty    ) * YW + 4 * tx + 4);
    float4 yD   = *reinterpret_cast<const float4*>(s_y + (ty + 2) * YW + 4 * tx + 4);
    float  yL   = s_y[(ty + 1) * YW + 4 * tx + 3];
    float  yR   = s_y[(ty + 1) * YW + 4 * tx + 8];

    float xtc[4]  = {xtC.x, xtC.y, xtC.z, xtC.w};
    float xtu[4]  = {xtU.x, xtU.y, xtU.z, xtU.w};
    float xtd[4]  = {xtD.x, xtD.y, xtD.z, xtD.w};
    float xttc[4] = {xttC.x, xttC.y, xttC.z, xttC.w};
    float spc[4]  = {spC.x, spC.y, spC.z, spC.w};
    float yc[4]   = {yC.x, yC.y, yC.z, yC.w};
    float yu[4]   = {yU.x, yU.y, yU.z, yU.w};
    float yd[4]   = {yD.x, yD.y, yD.z, yD.w};

    float x7v[4], x7p[4], xt4[4];

    #pragma unroll
    for (int j = 0; j < 4; j++) {
        int c = cb + j;
        float xl = (j == 0) ? xtL : xtc[j - 1];
        float xr = (j == 3) ? xtR : xtc[j + 1];
        float yl = (j == 0) ? yL  : yc[j - 1];
        float yr2 = (j == 3) ? yR : yc[j + 1];

        float coef = spc[j] * spc[j] * 0.0025f;     // DT^2/DX^2
        float base = 2.f * xtc[j] - xttc[j];
        bool interior = (r > 0) & (r < H - 1) & (c > 0) & (c < H - 1);

        float lap = xtu[j] + xtd[j] + xl + xr - 4.f * xtc[j];
        xt4[j] = interior ? (base + lap * coef) : 0.f;

        float lapy = yu[j] + yd[j] + yl + yr2 - 4.f * yc[j];
        float p = interior ? (base + lapy * coef) : yc[j];
        x7p[j] = p;

        float v = p;
        if (r == 0) v = 0.f;
        if (c == 0)     v = xtc[j] - 0.05f * spc[j] * (xtc[j] - xr);   // DT/DX
        if (r >= 1 && r <= H - 2 && c == H - r)
            v = s_xt[(ty + 1) * IN_W + 4 * tx + j + 3];                // xt[r-1,c-1]
        if (c == H - 1) v = xtc[j] - 0.05f * spc[j] * (xtc[j] - xl);
        if (r == H - 1) v = 0.f;
        x7v[j] = v;
    }

    size_t g = (size_t)r * H + cb;
    *reinterpret_cast<float4*>(out + 2 * (size_t)HH + g) = *reinterpret_cast<float4*>(x7v);
    *reinterpret_cast<float4*>(out + 5 * (size_t)HH + g) = *reinterpret_cast<float4*>(x7p);
    *reinterpret_cast<float4*>(out + 6 * (size_t)HH + g) = *reinterpret_cast<float4*>(xt4);

    // ---- folded observation scatter: block owning the pixel overrides plane 2.
    // __syncthreads orders the plane-2 STG above before the override below
    // within this block, so last-wins semantics match the reference.
    __syncthreads();
    if (tid < P) {
        int lx = loc_x[tid];
        if (lx != -1) {
            int lyv = loc_y[tid];
            if (lx >= r0 && lx < r0 + TH && lyv >= c0 && lyv < c0 + TW) {
                int id = dscalar(p_id, 1);
                size_t obs_off = (size_t)(id * bsize + step + 2) * HH;
                size_t gs = (size_t)lx * H + lyv;
                out[2 * (size_t)HH + gs] = ref_sol[obs_off + gs];
            }
        }
    }
}

extern "C" void kernel_launch(void* const* d_in, const int* in_sizes, int n_in,
                              void* d_out, int out_size)
{
    const float* ref_speed = (const float*)d_in[0];
    const float* batch     = (const float*)d_in[1];
    const float* x_tt      = (const float*)d_in[2];
    const float* x_t       = (const float*)d_in[3];
    const float* ref_sol   = (const float*)d_in[4];
    const float* conv_v    = (const float*)d_in[5];
    const float* conv_g    = (const float*)d_in[6];
    const float* conv_b    = (const float*)d_in[7];
    const int*   loc_x     = (const int*)d_in[8];
    const int*   loc_y     = (const int*)d_in[9];
    const int* p_bsize    = (n_in > 10) ? (const int*)d_in[10] : nullptr;
    const int* p_id       = (n_in > 11) ? (const int*)d_in[11] : nullptr;
    const int* p_flag     = (n_in > 12) ? (const int*)d_in[12] : nullptr;
    const int* p_flag_num = (n_in > 13) ? (const int*)d_in[13] : nullptr;

    float* out = (float*)d_out;
    int P = in_sizes[8];

    int n4 = HH / 4;
    pgonet_copy<<<(n4 + 255) / 256, 256>>>((const float4*)x_tt, (const float4*)x_t,
                                           (float4*)out);

    dim3 block(16, 32);
    dim3 grid(H / TW, H / TH);
    pgonet_main<<<grid, block>>>(ref_speed, batch,
                                 conv_v, conv_g, conv_b,
                                 ref_sol, loc_x, loc_y,
                                 p_bsize, p_id, p_flag, p_flag_num,
                                 out, P);
}

// round 4
// speedup vs baseline: 1.6177x; 1.1791x over previous
#include <cuda_runtime.h>
#include <math.h>

#define H 2048
#define HH (H*H)
#define TW 64                  // tile width (cols)
#define TH 32                  // tile height (rows)
#define IN_W 76                // input smem stride: cols c0-4 .. c0+71 (19 float4 groups)
#define IN_H 36                // rows r0-2 .. r0+33
#define IN_HW (IN_H * IN_W)
#define YW 72                  // y smem stride: sc = gy - (c0-3), sc in 0..71
#define YH 34                  // y rows: gyr = r0-1+ly, ly 0..33

__device__ __forceinline__ int dscalar(const int* p, int def) {
    return p ? p[0] : def;
}

__global__ __launch_bounds__(512, 3)
void pgonet_main(const float* __restrict__ ref_speed,
                 const float* __restrict__ batch,
                 const float* __restrict__ x_tt,
                 const float* __restrict__ x_t,
                 const float* __restrict__ conv_v,
                 const float* __restrict__ conv_g,
                 const float* __restrict__ conv_b,
                 const float* __restrict__ ref_sol,
                 const int*   __restrict__ loc_x,
                 const int*   __restrict__ loc_y,
                 const int* p_bsize, const int* p_id,
                 const int* p_flag, const int* p_flag_num,
                 float* __restrict__ out, int P)
{
    __shared__ float s_in[3 * IN_HW];   // ch0=xtt ch1=xt ch2=speed
    __shared__ float s_y[YH * YW];
    __shared__ float s_W[28];
    __shared__ float s_b;

    const int tx = threadIdx.x;   // 0..15 (float4 col group)
    const int ty = threadIdx.y;   // 0..31 (row)
    const int tid = ty * 16 + tx;
    const int r0 = blockIdx.y * TH;
    const int c0 = blockIdx.x * TW;

    const int bsize = dscalar(p_bsize, 10);
    const int ntb   = dscalar(p_flag, 1) - 1;
    const int step  = dscalar(p_flag_num, 1) - 1;
    const int i0    = ntb * bsize + step;
    const float* __restrict__ xtt_g = batch + (size_t)i0 * HH;
    const float* __restrict__ xt_g  = batch + (size_t)(i0 + 1) * HH;

    // ---- planes 0,1,3,4: pure copies (streaming; overlaps with staging) ----
    {
        const int r = r0 + ty;
        size_t g = (size_t)r * H + c0 + 4 * tx;
        float4 a = *reinterpret_cast<const float4*>(x_tt + g);
        float4 b = *reinterpret_cast<const float4*>(x_t + g);
        *reinterpret_cast<float4*>(out + g)                   = a;
        *reinterpret_cast<float4*>(out + HH + g)              = b;
        *reinterpret_cast<float4*>(out + 3 * (size_t)HH + g)  = a;
        *reinterpret_cast<float4*>(out + 4 * (size_t)HH + g)  = b;
    }

    if (tid == 0) {
        float ss = 0.f;
        #pragma unroll
        for (int i = 0; i < 27; i++) { float v = conv_v[i]; ss += v * v; }
        float scale = conv_g[0] / sqrtf(ss);
        #pragma unroll
        for (int i = 0; i < 27; i++) s_W[i] = conv_v[i] * scale;
        s_b = conv_b[0];
    }

    // ---- stage 3 x 36 x 76 floats as float4: 3*36*19 = 2052 groups ----
    for (int idx = tid; idx < 3 * IN_H * 19; idx += 512) {
        int ch = idx / (IN_H * 19);
        int k  = idx - ch * (IN_H * 19);
        int lr = k / 19, lq = k - lr * 19;
        int gr = r0 - 2 + lr;
        int gc = c0 - 4 + 4 * lq;
        float4 v = make_float4(0.f, 0.f, 0.f, 0.f);
        if (gr >= 0 && gr < H && gc >= 0 && gc + 3 < H) {
            const float* p = (ch == 0) ? xtt_g : ((ch == 1) ? xt_g : ref_speed);
            v = *reinterpret_cast<const float4*>(p + (size_t)gr * H + gc);
        }
        *reinterpret_cast<float4*>(&s_in[ch * IN_HW + lr * IN_W + 4 * lq]) = v;
    }
    __syncthreads();

    // ---- conv: 8-wide strips. strip (ly, q): y rows gyr=r0-1+ly,
    // outputs gy = c0-3+8q+k (k=0..7), taps ic = 8q+k..8q+k+2 from a 12-float
    // window at ic = 8q..8q+11 (3 aligned float4). 34*9 = 306 strips.
    const float bconv = s_b;
    if (tid < YH * 9) {
        int ly = tid / 9, q = tid - ly * 9;
        float acc[8];
        #pragma unroll
        for (int k = 0; k < 8; k++) acc[k] = bconv;
        #pragma unroll
        for (int ch = 0; ch < 3; ch++) {
            #pragma unroll
            for (int kh = 0; kh < 3; kh++) {
                const float4* rp = reinterpret_cast<const float4*>(
                    s_in + ch * IN_HW + (ly + kh) * IN_W + 8 * q);
                float4 A = rp[0], B = rp[1], C = rp[2];
                float t[12] = {A.x, A.y, A.z, A.w, B.x, B.y, B.z, B.w,
                               C.x, C.y, C.z, C.w};
                float w0 = s_W[ch * 9 + kh * 3 + 0];
                float w1 = s_W[ch * 9 + kh * 3 + 1];
                float w2 = s_W[ch * 9 + kh * 3 + 2];
                #pragma unroll
                for (int k = 0; k < 8; k++) {
                    acc[k] = fmaf(w0, t[k], acc[k]);
                    acc[k] = fmaf(w1, t[k + 1], acc[k]);
                    acc[k] = fmaf(w2, t[k + 2], acc[k]);
                }
            }
        }
        float4* yp = reinterpret_cast<float4*>(s_y + ly * YW + 8 * q);
        yp[0] = make_float4(acc[0], acc[1], acc[2], acc[3]);
        yp[1] = make_float4(acc[4], acc[5], acc[6], acc[7]);
    }
    __syncthreads();

    const float* s_xtt = s_in;
    const float* s_xt  = s_in + IN_HW;
    const float* s_sp  = s_in + 2 * IN_HW;

    const int r = r0 + ty;
    const int cb = c0 + 4 * tx;

    // xt / xtt / sp reads (center ic = 4tx+jj+4)
    float4 xtC  = *reinterpret_cast<const float4*>(s_xt  + (ty + 2) * IN_W + 4 * tx + 4);
    float4 xtU  = *reinterpret_cast<const float4*>(s_xt  + (ty + 1) * IN_W + 4 * tx + 4);
    float4 xtD  = *reinterpret_cast<const float4*>(s_xt  + (ty + 3) * IN_W + 4 * tx + 4);
    float  xtL  = s_xt[(ty + 2) * IN_W + 4 * tx + 3];
    float  xtR  = s_xt[(ty + 2) * IN_W + 4 * tx + 8];
    float4 xttC = *reinterpret_cast<const float4*>(s_xtt + (ty + 2) * IN_W + 4 * tx + 4);
    float4 spC  = *reinterpret_cast<const float4*>(s_sp  + (ty + 2) * IN_W + 4 * tx + 4);

    // y reads: sc = gy - c0 + 3; thread needs sc in [4tx+2, 4tx+8] -> two
    // aligned float4 per row at sc=4tx and 4tx+4, rows ty(up), ty+1(center), ty+2(down)
    float yc8[8], yu8[8], yd8[8];
    {
        const float4* pc = reinterpret_cast<const float4*>(s_y + (ty + 1) * YW + 4 * tx);
        const float4* pu = reinterpret_cast<const float4*>(s_y + (ty    ) * YW + 4 * tx);
        const float4* pd = reinterpret_cast<const float4*>(s_y + (ty + 2) * YW + 4 * tx);
        float4 c0v = pc[0], c1v = pc[1];
        float4 u0v = pu[0], u1v = pu[1];
        float4 d0v = pd[0], d1v = pd[1];
        yc8[0]=c0v.x; yc8[1]=c0v.y; yc8[2]=c0v.z; yc8[3]=c0v.w;
        yc8[4]=c1v.x; yc8[5]=c1v.y; yc8[6]=c1v.z; yc8[7]=c1v.w;
        yu8[0]=u0v.x; yu8[1]=u0v.y; yu8[2]=u0v.z; yu8[3]=u0v.w;
        yu8[4]=u1v.x; yu8[5]=u1v.y; yu8[6]=u1v.z; yu8[7]=u1v.w;
        yd8[0]=d0v.x; yd8[1]=d0v.y; yd8[2]=d0v.z; yd8[3]=d0v.w;
        yd8[4]=d1v.x; yd8[5]=d1v.y; yd8[6]=d1v.z; yd8[7]=d1v.w;
    }

    float xtc[4]  = {xtC.x, xtC.y, xtC.z, xtC.w};
    float xtu[4]  = {xtU.x, xtU.y, xtU.z, xtU.w};
    float xtd[4]  = {xtD.x, xtD.y, xtD.z, xtD.w};
    float xttc[4] = {xttC.x, xttC.y, xttC.z, xttC.w};
    float spc[4]  = {spC.x, spC.y, spC.z, spC.w};

    float x7v[4], x7p[4], xt4[4];

    #pragma unroll
    for (int j = 0; j < 4; j++) {
        int c = cb + j;
        float xl = (j == 0) ? xtL : xtc[j - 1];
        float xr = (j == 3) ? xtR : xtc[j + 1];
        float ycn = yc8[j + 3];            // center
        float yl  = yc8[j + 2];
        float yr2 = yc8[j + 4];
        float yun = yu8[j + 3];
        float ydn = yd8[j + 3];

        float coef = spc[j] * spc[j] * 0.0025f;     // (DT/DX)^2
        float base = 2.f * xtc[j] - xttc[j];
        bool interior = (r > 0) & (r < H - 1) & (c > 0) & (c < H - 1);

        float lap = xtu[j] + xtd[j] + xl + xr - 4.f * xtc[j];
        xt4[j] = interior ? (base + lap * coef) : 0.f;

        float lapy = yun + ydn + yl + yr2 - 4.f * ycn;
        float p = interior ? (base + lapy * coef) : ycn;
        x7p[j] = p;

        float v = p;
        if (r == 0) v = 0.f;
        if (c == 0)     v = xtc[j] - 0.05f * spc[j] * (xtc[j] - xr);   // DT/DX
        if (r >= 1 && r <= H - 2 && c == H - r)
            v = s_xt[(ty + 1) * IN_W + 4 * tx + j + 3];                // xt[r-1,c-1]
        if (c == H - 1) v = xtc[j] - 0.05f * spc[j] * (xtc[j] - xl);
        if (r == H - 1) v = 0.f;
        x7v[j] = v;
    }

    size_t g = (size_t)r * H + cb;
    *reinterpret_cast<float4*>(out + 2 * (size_t)HH + g) = *reinterpret_cast<float4*>(x7v);
    *reinterpret_cast<float4*>(out + 5 * (size_t)HH + g) = *reinterpret_cast<float4*>(x7p);
    *reinterpret_cast<float4*>(out + 6 * (size_t)HH + g) = *reinterpret_cast<float4*>(xt4);

    // ---- folded observation scatter: block owning the pixel overrides plane 2.
    __syncthreads();
    if (tid < P) {
        int lx = loc_x[tid];
        if (lx != -1) {
            int lyv = loc_y[tid];
            if (lx >= r0 && lx < r0 + TH && lyv >= c0 && lyv < c0 + TW) {
                int id = dscalar(p_id, 1);
                size_t obs_off = (size_t)(id * bsize + step + 2) * HH;
                size_t gs = (size_t)lx * H + lyv;
                out[2 * (size_t)HH + gs] = ref_sol[obs_off + gs];
            }
        }
    }
}

extern "C" void kernel_launch(void* const* d_in, const int* in_sizes, int n_in,
                              void* d_out, int out_size)
{
    const float* ref_speed = (const float*)d_in[0];
    const float* batch     = (const float*)d_in[1];
    const float* x_tt      = (const float*)d_in[2];
    const float* x_t       = (const float*)d_in[3];
    const float* ref_sol   = (const float*)d_in[4];
    const float* conv_v    = (const float*)d_in[5];
    const float* conv_g    = (const float*)d_in[6];
    const float* conv_b    = (const float*)d_in[7];
    const int*   loc_x     = (const int*)d_in[8];
    const int*   loc_y     = (const int*)d_in[9];
    const int* p_bsize    = (n_in > 10) ? (const int*)d_in[10] : nullptr;
    const int* p_id       = (n_in > 11) ? (const int*)d_in[11] : nullptr;
    const int* p_flag     = (n_in > 12) ? (const int*)d_in[12] : nullptr;
    const int* p_flag_num = (n_in > 13) ? (const int*)d_in[13] : nullptr;

    float* out = (float*)d_out;
    int P = in_sizes[8];

    dim3 block(16, 32);
    dim3 grid(H / TW, H / TH);
    pgonet_main<<<grid, block>>>(ref_speed, batch, x_tt, x_t,
                                 conv_v, conv_g, conv_b,
                                 ref_sol, loc_x, loc_y,
                                 p_bsize, p_id, p_flag, p_flag_num,
                                 out, P);
}

// round 5
// speedup vs baseline: 2.0181x; 1.2475x over previous
#include <cuda_runtime.h>
#include <math.h>
#include <stdint.h>

#define H 2048
#define HH (H*H)
#define TW 64                  // tile width (cols)
#define TH 16                  // tile height (rows)
#define IN_W 76                // input smem stride: cols c0-4 .. c0+71 (19 float4)
#define IN_H 20                // rows r0-2 .. r0+17
#define IN_HW (IN_H * IN_W)
#define YW 72                  // y smem stride: sc = gy - (c0-3)
#define YH 18                  // y rows: gyr = r0-1+ly, ly 0..17

__device__ __forceinline__ int dscalar(const int* p, int def) {
    return p ? p[0] : def;
}

__device__ __forceinline__ void cp_async16(uint32_t dst_smem, const void* src, int src_bytes) {
    asm volatile("cp.async.cg.shared.global [%0], [%1], 16, %2;\n"
                 :: "r"(dst_smem), "l"(src), "r"(src_bytes));
}
__device__ __forceinline__ void cp_async_commit_wait() {
    asm volatile("cp.async.commit_group;\n");
    asm volatile("cp.async.wait_group 0;\n" ::: "memory");
}

__global__ __launch_bounds__(256, 6)
void pgonet_main(const float* __restrict__ ref_speed,
                 const float* __restrict__ batch,
                 const float* __restrict__ x_tt,
                 const float* __restrict__ x_t,
                 const float* __restrict__ conv_v,
                 const float* __restrict__ conv_g,
                 const float* __restrict__ conv_b,
                 const float* __restrict__ ref_sol,
                 const int*   __restrict__ loc_x,
                 const int*   __restrict__ loc_y,
                 const int* p_bsize, const int* p_id,
                 const int* p_flag, const int* p_flag_num,
                 float* __restrict__ out, int P)
{
    __shared__ float s_in[3 * IN_HW];   // ch0=xtt ch1=xt ch2=speed
    __shared__ float s_y[YH * YW];
    __shared__ float s_W[28];
    __shared__ float s_b;

    const int tx = threadIdx.x & 15;      // 0..15 (float4 col group)
    const int ty = threadIdx.x >> 4;      // 0..15 (row)
    const int tid = threadIdx.x;
    const int r0 = blockIdx.y * TH;
    const int c0 = blockIdx.x * TW;

    const int bsize = dscalar(p_bsize, 10);
    const int ntb   = dscalar(p_flag, 1) - 1;
    const int step  = dscalar(p_flag_num, 1) - 1;
    const int i0    = ntb * bsize + step;
    const float* __restrict__ xtt_g = batch + (size_t)i0 * HH;
    const float* __restrict__ xt_g  = batch + (size_t)(i0 + 1) * HH;

    // ---- async-stage 3 x 20 x 76 floats: 3*20*19 = 1140 float4 groups ----
    uint32_t s_in_u32;
    {
        uint32_t a;
        asm("{ .reg .u64 t; cvta.to.shared.u64 t, %1; cvt.u32.u64 %0, t; }"
            : "=r"(a) : "l"(s_in));
        s_in_u32 = a;
    }
    #pragma unroll
    for (int it = 0; it < 5; it++) {
        int idx = tid + it * 256;
        if (idx < 3 * IN_H * 19) {
            int ch = idx / (IN_H * 19);
            int k  = idx - ch * (IN_H * 19);
            int lr = k / 19, lq = k - lr * 19;
            int gr = r0 - 2 + lr;
            int gc = c0 - 4 + 4 * lq;
            bool ok = (gr >= 0) && (gr < H) && (gc >= 0) && (gc + 3 < H);
            const float* p = (ch == 0) ? xtt_g : ((ch == 1) ? xt_g : ref_speed);
            const float* src = p + (ok ? ((size_t)gr * H + gc) : 0);
            uint32_t dst = s_in_u32 + 4u * (ch * IN_HW + lr * IN_W + 4 * lq);
            cp_async16(dst, src, ok ? 16 : 0);
        }
    }

    // ---- planes 0,1,3,4: pure copies (overlap with cp.async) ----
    {
        const int r = r0 + ty;
        size_t g = (size_t)r * H + c0 + 4 * tx;
        float4 a = *reinterpret_cast<const float4*>(x_tt + g);
        float4 b = *reinterpret_cast<const float4*>(x_t + g);
        *reinterpret_cast<float4*>(out + g)                  = a;
        *reinterpret_cast<float4*>(out + HH + g)             = b;
        *reinterpret_cast<float4*>(out + 3 * (size_t)HH + g) = a;
        *reinterpret_cast<float4*>(out + 4 * (size_t)HH + g) = b;
    }

    if (tid == 0) {
        float ss = 0.f;
        #pragma unroll
        for (int i = 0; i < 27; i++) { float v = conv_v[i]; ss += v * v; }
        float scale = conv_g[0] / sqrtf(ss);
        #pragma unroll
        for (int i = 0; i < 27; i++) s_W[i] = conv_v[i] * scale;
        s_b = conv_b[0];
    }

    cp_async_commit_wait();
    __syncthreads();

    const float* s_xtt = s_in;
    const float* s_xt  = s_in + IN_HW;
    const float* s_sp  = s_in + 2 * IN_HW;

    const int r = r0 + ty;
    const int cb = c0 + 4 * tx;

    // ---- phase A: x_t4 (plane 6) — store early, overlap with conv ----
    float4 xtC  = *reinterpret_cast<const float4*>(s_xt  + (ty + 2) * IN_W + 4 * tx + 4);
    float4 xtU  = *reinterpret_cast<const float4*>(s_xt  + (ty + 1) * IN_W + 4 * tx + 4);
    float4 xtD  = *reinterpret_cast<const float4*>(s_xt  + (ty + 3) * IN_W + 4 * tx + 4);
    float  xtL  = s_xt[(ty + 2) * IN_W + 4 * tx + 3];
    float  xtR  = s_xt[(ty + 2) * IN_W + 4 * tx + 8];
    float4 xttC = *reinterpret_cast<const float4*>(s_xtt + (ty + 2) * IN_W + 4 * tx + 4);
    float4 spC  = *reinterpret_cast<const float4*>(s_sp  + (ty + 2) * IN_W + 4 * tx + 4);

    float xtc[4]  = {xtC.x, xtC.y, xtC.z, xtC.w};
    float xtu[4]  = {xtU.x, xtU.y, xtU.z, xtU.w};
    float xtd[4]  = {xtD.x, xtD.y, xtD.z, xtD.w};
    float xttc[4] = {xttC.x, xttC.y, xttC.z, xttC.w};
    float spc[4]  = {spC.x, spC.y, spC.z, spC.w};

    float coef[4], base[4], xt4[4];
    #pragma unroll
    for (int j = 0; j < 4; j++) {
        int c = cb + j;
        float xl = (j == 0) ? xtL : xtc[j - 1];
        float xr = (j == 3) ? xtR : xtc[j + 1];
        coef[j] = spc[j] * spc[j] * 0.0025f;       // (DT/DX)^2
        base[j] = 2.f * xtc[j] - xttc[j];
        bool interior = (r > 0) & (r < H - 1) & (c > 0) & (c < H - 1);
        float lap = xtu[j] + xtd[j] + xl + xr - 4.f * xtc[j];
        xt4[j] = interior ? (base[j] + lap * coef[j]) : 0.f;
    }
    {
        size_t g = (size_t)r * H + cb;
        *reinterpret_cast<float4*>(out + 6 * (size_t)HH + g) = *reinterpret_cast<float4*>(xt4);
    }

    // ---- phase B: conv, 8-wide strips: 18 rows * 9 strips = 162 ----
    const float bconv = s_b;
    if (tid < YH * 9) {
        int ly = tid / 9, q = tid - ly * 9;
        float acc[8];
        #pragma unroll
        for (int k = 0; k < 8; k++) acc[k] = bconv;
        #pragma unroll
        for (int ch = 0; ch < 3; ch++) {
            #pragma unroll
            for (int kh = 0; kh < 3; kh++) {
                const float4* rp = reinterpret_cast<const float4*>(
                    s_in + ch * IN_HW + (ly + kh) * IN_W + 8 * q);
                float4 A = rp[0], B = rp[1], C = rp[2];
                float t[12] = {A.x, A.y, A.z, A.w, B.x, B.y, B.z, B.w,
                               C.x, C.y, C.z, C.w};
                float w0 = s_W[ch * 9 + kh * 3 + 0];
                float w1 = s_W[ch * 9 + kh * 3 + 1];
                float w2 = s_W[ch * 9 + kh * 3 + 2];
                #pragma unroll
                for (int k = 0; k < 8; k++) {
                    acc[k] = fmaf(w0, t[k], acc[k]);
                    acc[k] = fmaf(w1, t[k + 1], acc[k]);
                    acc[k] = fmaf(w2, t[k + 2], acc[k]);
                }
            }
        }
        float4* yp = reinterpret_cast<float4*>(s_y + ly * YW + 8 * q);
        yp[0] = make_float4(acc[0], acc[1], acc[2], acc[3]);
        yp[1] = make_float4(acc[4], acc[5], acc[6], acc[7]);
    }
    __syncthreads();

    // ---- phase C: x7 / x7_pre (planes 2, 5) ----
    float yc8[8], yu8[8], yd8[8];
    {
        const float4* pc = reinterpret_cast<const float4*>(s_y + (ty + 1) * YW + 4 * tx);
        const float4* pu = reinterpret_cast<const float4*>(s_y + (ty    ) * YW + 4 * tx);
        const float4* pd = reinterpret_cast<const float4*>(s_y + (ty + 2) * YW + 4 * tx);
        float4 c0v = pc[0], c1v = pc[1];
        float4 u0v = pu[0], u1v = pu[1];
        float4 d0v = pd[0], d1v = pd[1];
        yc8[0]=c0v.x; yc8[1]=c0v.y; yc8[2]=c0v.z; yc8[3]=c0v.w;
        yc8[4]=c1v.x; yc8[5]=c1v.y; yc8[6]=c1v.z; yc8[7]=c1v.w;
        yu8[0]=u0v.x; yu8[1]=u0v.y; yu8[2]=u0v.z; yu8[3]=u0v.w;
        yu8[4]=u1v.x; yu8[5]=u1v.y; yu8[6]=u1v.z; yu8[7]=u1v.w;
        yd8[0]=d0v.x; yd8[1]=d0v.y; yd8[2]=d0v.z; yd8[3]=d0v.w;
        yd8[4]=d1v.x; yd8[5]=d1v.y; yd8[6]=d1v.z; yd8[7]=d1v.w;
    }

    float x7v[4], x7p[4];
    #pragma unroll
    for (int j = 0; j < 4; j++) {
        int c = cb + j;
        float xl = (j == 0) ? xtL : xtc[j - 1];
        float xr = (j == 3) ? xtR : xtc[j + 1];
        float ycn = yc8[j + 3];
        float yl  = yc8[j + 2];
        float yr2 = yc8[j + 4];

        bool interior = (r > 0) & (r < H - 1) & (c > 0) & (c < H - 1);
        float lapy = yu8[j + 3] + yd8[j + 3] + yl + yr2 - 4.f * ycn;
        float p = interior ? (base[j] + lapy * coef[j]) : ycn;
        x7p[j] = p;

        float v = p;
        if (r == 0) v = 0.f;
        if (c == 0)     v = xtc[j] - 0.05f * spc[j] * (xtc[j] - xr);   // DT/DX
        if (r >= 1 && r <= H - 2 && c == H - r)
            v = s_xt[(ty + 1) * IN_W + 4 * tx + j + 3];                // xt[r-1,c-1]
        if (c == H - 1) v = xtc[j] - 0.05f * spc[j] * (xtc[j] - xl);
        if (r == H - 1) v = 0.f;
        x7v[j] = v;
    }

    size_t g = (size_t)r * H + cb;
    *reinterpret_cast<float4*>(out + 2 * (size_t)HH + g) = *reinterpret_cast<float4*>(x7v);
    *reinterpret_cast<float4*>(out + 5 * (size_t)HH + g) = *reinterpret_cast<float4*>(x7p);

    // ---- folded observation scatter (block owning pixel overrides plane 2) ----
    __syncthreads();
    if (tid < P) {
        int lx = loc_x[tid];
        if (lx != -1) {
            int lyv = loc_y[tid];
            if (lx >= r0 && lx < r0 + TH && lyv >= c0 && lyv < c0 + TW) {
                int id = dscalar(p_id, 1);
                size_t obs_off = (size_t)(id * bsize + step + 2) * HH;
                size_t gs = (size_t)lx * H + lyv;
                out[2 * (size_t)HH + gs] = ref_sol[obs_off + gs];
            }
        }
    }
}

extern "C" void kernel_launch(void* const* d_in, const int* in_sizes, int n_in,
                              void* d_out, int out_size)
{
    const float* ref_speed = (const float*)d_in[0];
    const float* batch     = (const float*)d_in[1];
    const float* x_tt      = (const float*)d_in[2];
    const float* x_t       = (const float*)d_in[3];
    const float* ref_sol   = (const float*)d_in[4];
    const float* conv_v    = (const float*)d_in[5];
    const float* conv_g    = (const float*)d_in[6];
    const float* conv_b    = (const float*)d_in[7];
    const int*   loc_x     = (const int*)d_in[8];
    const int*   loc_y     = (const int*)d_in[9];
    const int* p_bsize    = (n_in > 10) ? (const int*)d_in[10] : nullptr;
    const int* p_id       = (n_in > 11) ? (const int*)d_in[11] : nullptr;
    const int* p_flag     = (n_in > 12) ? (const int*)d_in[12] : nullptr;
    const int* p_flag_num = (n_in > 13) ? (const int*)d_in[13] : nullptr;

    float* out = (float*)d_out;
    int P = in_sizes[8];

    dim3 block(256);
    dim3 grid(H / TW, H / TH);
    pgonet_main<<<grid, block>>>(ref_speed, batch, x_tt, x_t,
                                 conv_v, conv_g, conv_b,
                                 ref_sol, loc_x, loc_y,
                                 p_bsize, p_id, p_flag, p_flag_num,
                                 out, P);
}